// round 1
// baseline (speedup 1.0000x reference)
#include <cuda_runtime.h>
#include <cstdint>

#define ZB   16384
#define NIN  127
#define NF   128      // N = NIN + 1
#define KOUT 128
#define DTS  2080
#define NNF  (NF * NF)  // 16384

// Scratch (device globals: no allocation allowed)
__device__ float g_M[KOUT * NNF];  // 8 MB: tf32-rounded (W @ T), row-major [K][N*N]
__device__ float g_F[ZB * NF];     // 8 MB: [ones, features]

__device__ __forceinline__ uint32_t f2tf32(float x) {
    uint32_t r;
    asm("cvt.rna.tf32.f32 %0, %1;" : "=r"(r) : "f"(x));
    return r;
}

__device__ __forceinline__ void mma_tf32(float c[4], const uint32_t a[4], const uint32_t b[2]) {
    asm volatile(
        "mma.sync.aligned.m16n8k8.row.col.f32.tf32.tf32.f32 "
        "{%0,%1,%2,%3}, {%4,%5,%6,%7}, {%8,%9}, {%0,%1,%2,%3};"
        : "+f"(c[0]), "+f"(c[1]), "+f"(c[2]), "+f"(c[3])
        : "r"(a[0]), "r"(a[1]), "r"(a[2]), "r"(a[3]), "r"(b[0]), "r"(b[1]));
}

// ---------------------------------------------------------------------------
// Kernel 0: F = [ones | features], [Z, 128]
// ---------------------------------------------------------------------------
__global__ void build_f_kernel(const float* __restrict__ feat) {
    int z = blockIdx.x;
    int c = threadIdx.x;
    g_F[z * NF + c] = (c == 0) ? 1.0f : feat[z * NIN + (c - 1)];
}

// ---------------------------------------------------------------------------
// Kernel 1: M = W @ T   ([128,2080] @ [2080,16384])
// Grid: 128 blocks over columns (128 cols each); 256 threads = 8 warps.
// Warp tile 32(m) x 64(n); mma m16n8k8 tf32; T tile transposed in smem.
// ---------------------------------------------------------------------------
__global__ void __launch_bounds__(256, 1) stage1_kernel(
        const float* __restrict__ W, const float* __restrict__ T) {
    __shared__ float Wsm[128 * 36];  // [m][k], stride 36 -> conflict-free frag reads
    __shared__ float Bsm[128 * 36];  // [n][t] transposed T tile

    const int tid  = threadIdx.x;
    const int lane = tid & 31;
    const int warp = tid >> 5;
    const int gid  = lane >> 2;   // groupID
    const int tig  = lane & 3;    // thread-in-group
    const int wm   = warp >> 1;   // 0..3
    const int wn   = warp & 1;    // 0..1
    const int colbase = blockIdx.x * 128;

    float acc[2][8][4];
#pragma unroll
    for (int mf = 0; mf < 2; mf++)
#pragma unroll
        for (int nf = 0; nf < 8; nf++)
#pragma unroll
            for (int q = 0; q < 4; q++) acc[mf][nf][q] = 0.0f;

    for (int kk = 0; kk < DTS; kk += 32) {   // 2080 = 65 * 32
        __syncthreads();
#pragma unroll
        for (int e = tid; e < 128 * 32; e += 256) {
            int m = e >> 5, k = e & 31;
            Wsm[m * 36 + k] = W[m * DTS + kk + k];
        }
#pragma unroll
        for (int e = tid; e < 32 * 128; e += 256) {
            int t = e >> 7, n = e & 127;
            Bsm[n * 36 + t] = T[(kk + t) * NNF + colbase + n];
        }
        __syncthreads();

#pragma unroll
        for (int ks = 0; ks < 4; ks++) {
            uint32_t breg[8][2];
#pragma unroll
            for (int nf = 0; nf < 8; nf++) {
                int n0 = wn * 64 + nf * 8 + gid;
                breg[nf][0] = f2tf32(Bsm[n0 * 36 + ks * 8 + tig]);
                breg[nf][1] = f2tf32(Bsm[n0 * 36 + ks * 8 + tig + 4]);
            }
#pragma unroll
            for (int mf = 0; mf < 2; mf++) {
                int r0 = wm * 32 + mf * 16 + gid;
                uint32_t a[4];
                a[0] = f2tf32(Wsm[r0 * 36 + ks * 8 + tig]);
                a[1] = f2tf32(Wsm[(r0 + 8) * 36 + ks * 8 + tig]);
                a[2] = f2tf32(Wsm[r0 * 36 + ks * 8 + tig + 4]);
                a[3] = f2tf32(Wsm[(r0 + 8) * 36 + ks * 8 + tig + 4]);
#pragma unroll
                for (int nf = 0; nf < 8; nf++)
                    mma_tf32(acc[mf][nf], a, breg[nf]);
            }
        }
    }

    // Store tf32-rounded so stage 2 can feed M straight into the MMA losslessly.
#pragma unroll
    for (int mf = 0; mf < 2; mf++) {
        int r0 = wm * 32 + mf * 16 + gid;
#pragma unroll
        for (int nf = 0; nf < 8; nf++) {
            int c0 = colbase + wn * 64 + nf * 8 + 2 * tig;
            g_M[r0 * NNF + c0]           = __uint_as_float(f2tf32(acc[mf][nf][0]));
            g_M[r0 * NNF + c0 + 1]       = __uint_as_float(f2tf32(acc[mf][nf][1]));
            g_M[(r0 + 8) * NNF + c0]     = __uint_as_float(f2tf32(acc[mf][nf][2]));
            g_M[(r0 + 8) * NNF + c0 + 1] = __uint_as_float(f2tf32(acc[mf][nf][3]));
        }
    }
}

// ---------------------------------------------------------------------------
// Kernel 2: out[z,k] = sum_{i,j} f[z,i] f[z,j] M[k, i*128+j]
// Grid: 128 z-tiles of 128 rows; 256 threads = 8 warps (warp tile 32z x 64k).
// Per i: A_i[z,j] = f[z,i]*f[z,j] built in registers (rounded to tf32 once),
// B_i = M[:, i*128 : i*128+128] staged via cp.async double buffer (L2-resident).
// ---------------------------------------------------------------------------
#define FSTR 132
#define S2_SMEM (3 * 128 * FSTR * 4)   // fsm + 2 B buffers = 202752 B

__global__ void __launch_bounds__(256, 1) stage2_kernel(float* __restrict__ out) {
    extern __shared__ float sm[];
    float* fsm = sm;                  // [128][FSTR]
    float* bufs[2] = { sm + 128 * FSTR, sm + 2 * 128 * FSTR };

    const int tid  = threadIdx.x;
    const int lane = tid & 31;
    const int warp = tid >> 5;
    const int gid  = lane >> 2;
    const int tig  = lane & 3;
    const int wm   = warp >> 1;
    const int wn   = warp & 1;
    const int zbase = blockIdx.x * 128;

    // Stage f tile [128 z][128 c]
    for (int e = tid; e < 128 * 128; e += 256) {
        int z = e >> 7, c = e & 127;
        fsm[z * FSTR + c] = g_F[(zbase + z) * NF + c];
    }

    float acc[2][8][4];
#pragma unroll
    for (int mf = 0; mf < 2; mf++)
#pragma unroll
        for (int nf = 0; nf < 8; nf++)
#pragma unroll
            for (int q = 0; q < 4; q++) acc[mf][nf][q] = 0.0f;

    auto prefetch = [&](int i, float* buf) {
#pragma unroll
        for (int e = tid; e < 4096; e += 256) {      // 128 rows * 32 x 16B chunks
            int kk = e >> 5, cs = e & 31;
            uint32_t dst = (uint32_t)__cvta_generic_to_shared(buf + kk * FSTR + cs * 4);
            size_t src = __cvta_generic_to_global(g_M + kk * NNF + i * 128 + cs * 4);
            asm volatile("cp.async.cg.shared.global [%0], [%1], 16;" :: "r"(dst), "l"(src));
        }
        asm volatile("cp.async.commit_group;" ::: "memory");
    };

    prefetch(0, bufs[0]);

    for (int i = 0; i < 128; ++i) {
        float* cur = bufs[i & 1];
        if (i + 1 < 128) {
            prefetch(i + 1, bufs[(i + 1) & 1]);
            asm volatile("cp.async.wait_group 1;" ::: "memory");
        } else {
            asm volatile("cp.async.wait_group 0;" ::: "memory");
        }
        __syncthreads();

        float fi[2][2];
#pragma unroll
        for (int mf = 0; mf < 2; mf++) {
            int r0 = wm * 32 + mf * 16 + gid;
            fi[mf][0] = fsm[r0 * FSTR + i];
            fi[mf][1] = fsm[(r0 + 8) * FSTR + i];
        }

#pragma unroll
        for (int ks = 0; ks < 16; ks++) {
            const int jb = ks * 8;
            uint32_t breg[8][2];
#pragma unroll
            for (int nf = 0; nf < 8; nf++) {
                int n0 = wn * 64 + nf * 8 + gid;
                breg[nf][0] = __float_as_uint(cur[n0 * FSTR + jb + tig]);      // already tf32
                breg[nf][1] = __float_as_uint(cur[n0 * FSTR + jb + tig + 4]);
            }
#pragma unroll
            for (int mf = 0; mf < 2; mf++) {
                int r0 = wm * 32 + mf * 16 + gid;
                int j0 = jb + tig;
                float fj00 = fsm[r0 * FSTR + j0];
                float fj10 = fsm[(r0 + 8) * FSTR + j0];
                float fj01 = fsm[r0 * FSTR + j0 + 4];
                float fj11 = fsm[(r0 + 8) * FSTR + j0 + 4];
                uint32_t a[4];
                a[0] = f2tf32(fi[mf][0] * fj00);   // one rounding of the fp32 product
                a[1] = f2tf32(fi[mf][1] * fj10);
                a[2] = f2tf32(fi[mf][0] * fj01);
                a[3] = f2tf32(fi[mf][1] * fj11);
#pragma unroll
                for (int nf = 0; nf < 8; nf++)
                    mma_tf32(acc[mf][nf], a, breg[nf]);
            }
        }
        __syncthreads();
    }

    // Epilogue: out[z, k], fp32
#pragma unroll
    for (int mf = 0; mf < 2; mf++) {
        int r0 = wm * 32 + mf * 16 + gid;
#pragma unroll
        for (int nf = 0; nf < 8; nf++) {
            int c0 = wn * 64 + nf * 8 + 2 * tig;
            out[(zbase + r0) * KOUT + c0]         = acc[mf][nf][0];
            out[(zbase + r0) * KOUT + c0 + 1]     = acc[mf][nf][1];
            out[(zbase + r0 + 8) * KOUT + c0]     = acc[mf][nf][2];
            out[(zbase + r0 + 8) * KOUT + c0 + 1] = acc[mf][nf][3];
        }
    }
}

// ---------------------------------------------------------------------------
extern "C" void kernel_launch(void* const* d_in, const int* in_sizes, int n_in,
                              void* d_out, int out_size) {
    const float* feat = nullptr;
    const float* W    = nullptr;
    const float* T    = nullptr;
    for (int i = 0; i < n_in; i++) {
        if      (in_sizes[i] == ZB * NIN)   feat = (const float*)d_in[i];
        else if (in_sizes[i] == KOUT * DTS) W    = (const float*)d_in[i];
        else if (in_sizes[i] == DTS * NNF)  T    = (const float*)d_in[i];
    }
    float* out = (float*)d_out;

    cudaFuncSetAttribute(stage2_kernel,
                         cudaFuncAttributeMaxDynamicSharedMemorySize, S2_SMEM);

    build_f_kernel<<<ZB, NF>>>(feat);
    stage1_kernel<<<128, 256>>>(W, T);
    stage2_kernel<<<128, 256, S2_SMEM>>>(out);
}

// round 2
// speedup vs baseline: 1.4129x; 1.4129x over previous
#include <cuda_runtime.h>
#include <cstdint>

#define ZB   16384
#define NIN  127
#define NF   128      // N = NIN + 1
#define KOUT 128
#define DTS  2080
#define NNF  (NF * NF)  // 16384
#define RPAIR 8256      // number of (i<=j) pairs
#define RPAD  8320      // padded to 65*128
#define NCHUNK 65
#define FSTR 132

// Scratch (device globals: no allocation allowed)
__device__ __align__(16) float    g_M[KOUT * NNF];            // 8 MB: tf32-rounded W@T
__device__ __align__(16) float    g_B[NCHUNK * 128 * 128];    // 4.26 MB: packed+permuted sym M
__device__ __align__(16) uint32_t g_pair[RPAD];               // i | (j<<16)

__device__ __forceinline__ uint32_t f2tf32(float x) {
    uint32_t r;
    asm("cvt.rna.tf32.f32 %0, %1;" : "=r"(r) : "f"(x));
    return r;
}

__device__ __forceinline__ void mma_tf32(float c[4], const uint32_t a[4], const uint32_t b[2]) {
    asm volatile(
        "mma.sync.aligned.m16n8k8.row.col.f32.tf32.tf32.f32 "
        "{%0,%1,%2,%3}, {%4,%5,%6,%7}, {%8,%9}, {%0,%1,%2,%3};"
        : "+f"(c[0]), "+f"(c[1]), "+f"(c[2]), "+f"(c[3])
        : "r"(a[0]), "r"(a[1]), "r"(a[2]), "r"(a[3]), "r"(b[0]), "r"(b[1]));
}

// ---------------------------------------------------------------------------
// Kernel 1: M = W @ T   ([128,2080] @ [2080,16384])  -- unchanged (known good)
// ---------------------------------------------------------------------------
__global__ void __launch_bounds__(256, 1) stage1_kernel(
        const float* __restrict__ W, const float* __restrict__ T) {
    __shared__ float Wsm[128 * 36];
    __shared__ float Bsm[128 * 36];

    const int tid  = threadIdx.x;
    const int lane = tid & 31;
    const int warp = tid >> 5;
    const int gid  = lane >> 2;
    const int tig  = lane & 3;
    const int wm   = warp >> 1;
    const int wn   = warp & 1;
    const int colbase = blockIdx.x * 128;

    float acc[2][8][4];
#pragma unroll
    for (int mf = 0; mf < 2; mf++)
#pragma unroll
        for (int nf = 0; nf < 8; nf++)
#pragma unroll
            for (int q = 0; q < 4; q++) acc[mf][nf][q] = 0.0f;

    for (int kk = 0; kk < DTS; kk += 32) {
        __syncthreads();
#pragma unroll
        for (int e = tid; e < 128 * 32; e += 256) {
            int m = e >> 5, k = e & 31;
            Wsm[m * 36 + k] = W[m * DTS + kk + k];
        }
#pragma unroll
        for (int e = tid; e < 32 * 128; e += 256) {
            int t = e >> 7, n = e & 127;
            Bsm[n * 36 + t] = T[(kk + t) * NNF + colbase + n];
        }
        __syncthreads();

#pragma unroll
        for (int ks = 0; ks < 4; ks++) {
            uint32_t breg[8][2];
#pragma unroll
            for (int nf = 0; nf < 8; nf++) {
                int n0 = wn * 64 + nf * 8 + gid;
                breg[nf][0] = f2tf32(Bsm[n0 * 36 + ks * 8 + tig]);
                breg[nf][1] = f2tf32(Bsm[n0 * 36 + ks * 8 + tig + 4]);
            }
#pragma unroll
            for (int mf = 0; mf < 2; mf++) {
                int r0 = wm * 32 + mf * 16 + gid;
                uint32_t a[4];
                a[0] = f2tf32(Wsm[r0 * 36 + ks * 8 + tig]);
                a[1] = f2tf32(Wsm[(r0 + 8) * 36 + ks * 8 + tig]);
                a[2] = f2tf32(Wsm[r0 * 36 + ks * 8 + tig + 4]);
                a[3] = f2tf32(Wsm[(r0 + 8) * 36 + ks * 8 + tig + 4]);
#pragma unroll
                for (int nf = 0; nf < 8; nf++)
                    mma_tf32(acc[mf][nf], a, breg[nf]);
            }
        }
    }

#pragma unroll
    for (int mf = 0; mf < 2; mf++) {
        int r0 = wm * 32 + mf * 16 + gid;
#pragma unroll
        for (int nf = 0; nf < 8; nf++) {
            int c0 = colbase + wn * 64 + nf * 8 + 2 * tig;
            g_M[r0 * NNF + c0]           = __uint_as_float(f2tf32(acc[mf][nf][0]));
            g_M[r0 * NNF + c0 + 1]       = __uint_as_float(f2tf32(acc[mf][nf][1]));
            g_M[(r0 + 8) * NNF + c0]     = __uint_as_float(f2tf32(acc[mf][nf][2]));
            g_M[(r0 + 8) * NNF + c0 + 1] = __uint_as_float(f2tf32(acc[mf][nf][3]));
        }
    }
}

// ---------------------------------------------------------------------------
// Pair table: r -> (i, j) with i <= j, i-major.  base(i) = 128i - i(i-1)/2
// ---------------------------------------------------------------------------
__global__ void build_pairs_kernel() {
    int i = blockIdx.x, j = threadIdx.x;
    if (j >= i) {
        int r = i * NF - (i * (i - 1)) / 2 + (j - i);
        g_pair[r] = (uint32_t)i | ((uint32_t)j << 16);
    }
    if (i == 0 && j < RPAD - RPAIR) g_pair[RPAIR + j] = 0;  // padding -> (0,0), B=0
}

// ---------------------------------------------------------------------------
// Pack: Bpack[k, r] = M[k,i,j] + (i<j ? M[k,j,i] : 0), tf32-rounded, stored in
// PERMUTED fragment order so stage2 can LDS.128 its B fragments:
// within each 128-r chunk, word w = ksp*16 + tig*4 + e holds
//   r_off = (2*ksp + (e>>1))*8 + tig + 4*(e&1)
// ---------------------------------------------------------------------------
__global__ void pack_kernel() {
    int c = blockIdx.x, k = blockIdx.y, w = threadIdx.x;
    int ksp = w >> 4, q = (w >> 2) & 3, e = w & 3;
    int ks = 2 * ksp + (e >> 1);
    int roff = ks * 8 + q + 4 * (e & 1);
    int r = c * 128 + roff;
    float v = 0.0f;
    if (r < RPAIR) {
        uint32_t p = g_pair[r];
        int i = p & 0xFFFF, j = p >> 16;
        v = g_M[k * NNF + i * NF + j];
        if (i != j) v += g_M[k * NNF + j * NF + i];
    }
    g_B[c * 16384 + k * 128 + w] = __uint_as_float(f2tf32(v));
}

// ---------------------------------------------------------------------------
// Stage 2: out[z,k] = sum_r f[z,i_r] f[z,j_r] * Bpack[k,r], r over 8256 pairs
// Grid: 128 z-tiles of 128; 256 threads = 8 warps (warp tile 32z x 64k).
// B chunks (64KB, L2-resident) double-buffered via cp.async; A built in regs.
// ---------------------------------------------------------------------------
#define S2_SMEM ((3 * 128 * FSTR + 256) * 4)   // fsm + 2 B bufs + 2 pair bufs

__global__ void __launch_bounds__(256, 1) stage2_kernel(
        const float* __restrict__ feat, float* __restrict__ out) {
    extern __shared__ float sm[];
    float* fsm = sm;                               // [128][FSTR]
    float* bufB[2] = { sm + 128 * FSTR, sm + 2 * 128 * FSTR };
    uint32_t* pbuf = (uint32_t*)(sm + 3 * 128 * FSTR);  // [2][128]

    const int tid  = threadIdx.x;
    const int lane = tid & 31;
    const int warp = tid >> 5;
    const int gid  = lane >> 2;
    const int tig  = lane & 3;
    const int wm   = warp >> 1;
    const int wn   = warp & 1;
    const int zbase = blockIdx.x * 128;

    // Stage f tile [128 z][128 c], ones column fused in (no build_f kernel)
    for (int e = tid; e < 128 * 128; e += 256) {
        int z = e >> 7, c = e & 127;
        fsm[z * FSTR + c] =
            (c == 0) ? 1.0f : feat[(size_t)(zbase + z) * NIN + (c - 1)];
    }

    float acc[2][8][4];
#pragma unroll
    for (int mf = 0; mf < 2; mf++)
#pragma unroll
        for (int nf = 0; nf < 8; nf++)
#pragma unroll
            for (int q = 0; q < 4; q++) acc[mf][nf][q] = 0.0f;

    auto prefetch = [&](int c, int bi) {
        float* buf = bufB[bi];
#pragma unroll
        for (int e = tid; e < 4096; e += 256) {    // 128 k-rows * 32 x 16B
            int kk = e >> 5, cs = e & 31;
            uint32_t dst = (uint32_t)__cvta_generic_to_shared(buf + kk * FSTR + cs * 4);
            size_t src = (size_t)__cvta_generic_to_global(g_B + c * 16384 + kk * 128 + cs * 4);
            asm volatile("cp.async.cg.shared.global [%0], [%1], 16;" :: "r"(dst), "l"(src));
        }
        if (tid < 32) {
            uint32_t dst = (uint32_t)__cvta_generic_to_shared(pbuf + bi * 128 + tid * 4);
            size_t src = (size_t)__cvta_generic_to_global(g_pair + c * 128 + tid * 4);
            asm volatile("cp.async.ca.shared.global [%0], [%1], 16;" :: "r"(dst), "l"(src));
        }
        asm volatile("cp.async.commit_group;" ::: "memory");
    };

    prefetch(0, 0);

    for (int c = 0; c < NCHUNK; ++c) {
        float* cur = bufB[c & 1];
        const uint32_t* pcur = pbuf + (c & 1) * 128;
        if (c + 1 < NCHUNK) {
            prefetch(c + 1, (c + 1) & 1);
            asm volatile("cp.async.wait_group 1;" ::: "memory");
        } else {
            asm volatile("cp.async.wait_group 0;" ::: "memory");
        }
        __syncthreads();

#pragma unroll
        for (int ksp = 0; ksp < 8; ksp++) {
            uint32_t bq[8][4];
#pragma unroll
            for (int nf = 0; nf < 8; nf++) {
                int n0 = wn * 64 + nf * 8 + gid;
                float4 v = *(const float4*)(cur + n0 * FSTR + ksp * 16 + tig * 4);
                bq[nf][0] = __float_as_uint(v.x);
                bq[nf][1] = __float_as_uint(v.y);
                bq[nf][2] = __float_as_uint(v.z);
                bq[nf][3] = __float_as_uint(v.w);
            }
#pragma unroll
            for (int s = 0; s < 2; s++) {
                int ks = 2 * ksp + s;
                uint32_t u1 = pcur[ks * 8 + tig];
                uint32_t u2 = pcur[ks * 8 + tig + 4];
                int i1 = u1 & 0xFFFF, j1 = u1 >> 16;
                int i2 = u2 & 0xFFFF, j2 = u2 >> 16;
#pragma unroll
                for (int mf = 0; mf < 2; mf++) {
                    int rA = wm * 32 + mf * 16 + gid;
                    const float* fA = fsm + rA * FSTR;
                    const float* fB = fA + 8 * FSTR;
                    uint32_t a[4];
                    a[0] = f2tf32(fA[i1] * fA[j1]);   // one fp32-product rounding
                    a[1] = f2tf32(fB[i1] * fB[j1]);
                    a[2] = f2tf32(fA[i2] * fA[j2]);
                    a[3] = f2tf32(fB[i2] * fB[j2]);
#pragma unroll
                    for (int nf = 0; nf < 8; nf++) {
                        uint32_t bb[2] = { bq[nf][2 * s], bq[nf][2 * s + 1] };
                        mma_tf32(acc[mf][nf], a, bb);
                    }
                }
            }
        }
        __syncthreads();
    }

    // Epilogue: out[z, k], fp32
#pragma unroll
    for (int mf = 0; mf < 2; mf++) {
        int r0 = wm * 32 + mf * 16 + gid;
#pragma unroll
        for (int nf = 0; nf < 8; nf++) {
            int c0 = wn * 64 + nf * 8 + 2 * tig;
            out[(zbase + r0) * KOUT + c0]         = acc[mf][nf][0];
            out[(zbase + r0) * KOUT + c0 + 1]     = acc[mf][nf][1];
            out[(zbase + r0 + 8) * KOUT + c0]     = acc[mf][nf][2];
            out[(zbase + r0 + 8) * KOUT + c0 + 1] = acc[mf][nf][3];
        }
    }
}

// ---------------------------------------------------------------------------
extern "C" void kernel_launch(void* const* d_in, const int* in_sizes, int n_in,
                              void* d_out, int out_size) {
    const float* feat = nullptr;
    const float* W    = nullptr;
    const float* T    = nullptr;
    for (int i = 0; i < n_in; i++) {
        if      (in_sizes[i] == ZB * NIN)   feat = (const float*)d_in[i];
        else if (in_sizes[i] == KOUT * DTS) W    = (const float*)d_in[i];
        else if (in_sizes[i] == DTS * NNF)  T    = (const float*)d_in[i];
    }
    float* out = (float*)d_out;

    cudaFuncSetAttribute(stage2_kernel,
                         cudaFuncAttributeMaxDynamicSharedMemorySize, S2_SMEM);

    build_pairs_kernel<<<128, 128>>>();
    stage1_kernel<<<128, 256>>>(W, T);
    pack_kernel<<<dim3(NCHUNK, KOUT), 128>>>();
    stage2_kernel<<<128, 256, S2_SMEM>>>(feat, out);
}

// round 3
// speedup vs baseline: 1.4355x; 1.0160x over previous
#include <cuda_runtime.h>
#include <cstdint>

#define ZB   16384
#define NIN  127
#define NF   128
#define KOUT 128
#define DTS  2080
#define NNF  (NF * NF)
#define RPAIR 8256
#define RPAD  8320          // 65 * 128
#define NCHUNK 65
#define NHALF  130          // 64-r half chunks

// Scratch (device globals)
__device__ __align__(16) float    g_M[KOUT * NNF];              // 8 MB tf32 W@T
__device__ __align__(16) float    g_B[NHALF * 128 * 64];        // packed sym M, permuted, half-chunk major
__device__ __align__(16) uint32_t g_pair[RPAD];                 // i | (j<<16)

__device__ __forceinline__ uint32_t f2tf32(float x) {
    uint32_t r;
    asm("cvt.rna.tf32.f32 %0, %1;" : "=r"(r) : "f"(x));
    return r;
}

__device__ __forceinline__ void mma_tf32(float c[4], const uint32_t a[4], const uint32_t b[2]) {
    asm volatile(
        "mma.sync.aligned.m16n8k8.row.col.f32.tf32.tf32.f32 "
        "{%0,%1,%2,%3}, {%4,%5,%6,%7}, {%8,%9}, {%0,%1,%2,%3};"
        : "+f"(c[0]), "+f"(c[1]), "+f"(c[2]), "+f"(c[3])
        : "r"(a[0]), "r"(a[1]), "r"(a[2]), "r"(a[3]), "r"(b[0]), "r"(b[1]));
}

// ---------------------------------------------------------------------------
// Kernel 1: M = W @ T  (unchanged, known good)
// ---------------------------------------------------------------------------
__global__ void __launch_bounds__(256, 1) stage1_kernel(
        const float* __restrict__ W, const float* __restrict__ T) {
    __shared__ float Wsm[128 * 36];
    __shared__ float Bsm[128 * 36];

    const int tid  = threadIdx.x;
    const int lane = tid & 31;
    const int warp = tid >> 5;
    const int gid  = lane >> 2;
    const int tig  = lane & 3;
    const int wm   = warp >> 1;
    const int wn   = warp & 1;
    const int colbase = blockIdx.x * 128;

    float acc[2][8][4];
#pragma unroll
    for (int mf = 0; mf < 2; mf++)
#pragma unroll
        for (int nf = 0; nf < 8; nf++)
#pragma unroll
            for (int q = 0; q < 4; q++) acc[mf][nf][q] = 0.0f;

    for (int kk = 0; kk < DTS; kk += 32) {
        __syncthreads();
#pragma unroll
        for (int e = tid; e < 128 * 32; e += 256) {
            int m = e >> 5, k = e & 31;
            Wsm[m * 36 + k] = W[m * DTS + kk + k];
        }
#pragma unroll
        for (int e = tid; e < 32 * 128; e += 256) {
            int t = e >> 7, n = e & 127;
            Bsm[n * 36 + t] = T[(kk + t) * NNF + colbase + n];
        }
        __syncthreads();

#pragma unroll
        for (int ks = 0; ks < 4; ks++) {
            uint32_t breg[8][2];
#pragma unroll
            for (int nf = 0; nf < 8; nf++) {
                int n0 = wn * 64 + nf * 8 + gid;
                breg[nf][0] = f2tf32(Bsm[n0 * 36 + ks * 8 + tig]);
                breg[nf][1] = f2tf32(Bsm[n0 * 36 + ks * 8 + tig + 4]);
            }
#pragma unroll
            for (int mf = 0; mf < 2; mf++) {
                int r0 = wm * 32 + mf * 16 + gid;
                uint32_t a[4];
                a[0] = f2tf32(Wsm[r0 * 36 + ks * 8 + tig]);
                a[1] = f2tf32(Wsm[(r0 + 8) * 36 + ks * 8 + tig]);
                a[2] = f2tf32(Wsm[r0 * 36 + ks * 8 + tig + 4]);
                a[3] = f2tf32(Wsm[(r0 + 8) * 36 + ks * 8 + tig + 4]);
#pragma unroll
                for (int nf = 0; nf < 8; nf++)
                    mma_tf32(acc[mf][nf], a, breg[nf]);
            }
        }
    }

#pragma unroll
    for (int mf = 0; mf < 2; mf++) {
        int r0 = wm * 32 + mf * 16 + gid;
#pragma unroll
        for (int nf = 0; nf < 8; nf++) {
            int c0 = colbase + wn * 64 + nf * 8 + 2 * tig;
            g_M[r0 * NNF + c0]           = __uint_as_float(f2tf32(acc[mf][nf][0]));
            g_M[r0 * NNF + c0 + 1]       = __uint_as_float(f2tf32(acc[mf][nf][1]));
            g_M[(r0 + 8) * NNF + c0]     = __uint_as_float(f2tf32(acc[mf][nf][2]));
            g_M[(r0 + 8) * NNF + c0 + 1] = __uint_as_float(f2tf32(acc[mf][nf][3]));
        }
    }
}

// ---------------------------------------------------------------------------
// Pair table: r -> (i, j), i <= j, i-major
// ---------------------------------------------------------------------------
__global__ void build_pairs_kernel() {
    int i = blockIdx.x, j = threadIdx.x;
    if (j >= i) {
        int r = i * NF - (i * (i - 1)) / 2 + (j - i);
        g_pair[r] = (uint32_t)i | ((uint32_t)j << 16);
    }
    if (i == 0 && j < RPAD - RPAIR) g_pair[RPAIR + j] = 0;
}

// ---------------------------------------------------------------------------
// Pack: Bpack[k, r] = M[k,i,j] (+ M[k,j,i] if i<j), tf32, permuted half-chunk
// layout: g_B[h][k][w], w = klp*16 + tig*4 + e encodes
//   r = h*64 + (2*klp + (e>>1))*8 + tig + 4*(e&1)
// ---------------------------------------------------------------------------
__global__ void pack_kernel() {
    int h = blockIdx.x, k = blockIdx.y, w = threadIdx.x;   // w in [0,64)
    int klp = w >> 4, q = (w >> 2) & 3, e = w & 3;
    int r = h * 64 + (2 * klp + (e >> 1)) * 8 + q + 4 * (e & 1);
    float v = 0.0f;
    if (r < RPAIR) {
        uint32_t p = g_pair[r];
        int i = p & 0xFFFF, j = p >> 16;
        v = g_M[k * NNF + i * NF + j];
        if (i != j) v += g_M[k * NNF + j * NF + i];
    }
    g_B[(h * 128 + k) * 64 + w] = __uint_as_float(f2tf32(v));
}

// ---------------------------------------------------------------------------
// Stage 2 with cooperative fragment-permuted A-tile build.
// SMEM: fsm [128][129] | A_sm [16384 words, fragment order] | Bh [2][128][80] | pbuf [2][128]
// ---------------------------------------------------------------------------
#define FSTRF 129
#define BSTR  80
#define FSM_WORDS  (128 * FSTRF)          // 16512
#define A_WORDS    16384
#define BH_WORDS   (128 * BSTR)           // 10240
#define S2_SMEM ((FSM_WORDS + A_WORDS + 2 * BH_WORDS + 256) * 4)  // 214528 B

__global__ void __launch_bounds__(256, 1) stage2_kernel(
        const float* __restrict__ feat, float* __restrict__ out) {
    extern __shared__ float sm[];
    float*    fsm  = sm;
    float*    A_sm = sm + FSM_WORDS;
    float*    bh0  = A_sm + A_WORDS;
    float*    bh1  = bh0 + BH_WORDS;
    uint32_t* pbuf = (uint32_t*)(bh1 + BH_WORDS);   // [2][128]

    const int tid  = threadIdx.x;
    const int lane = tid & 31;
    const int warp = tid >> 5;
    const int gid  = lane >> 2;
    const int tig  = lane & 3;
    const int wm   = warp >> 1;
    const int wn   = warp & 1;
    const int zbase = blockIdx.x * 128;

    // Stage f tile (ones column fused)
    for (int e = tid; e < 128 * 128; e += 256) {
        int z = e >> 7, c = e & 127;
        fsm[z * FSTRF + c] =
            (c == 0) ? 1.0f : feat[(size_t)(zbase + z) * NIN + (c - 1)];
    }

    float acc[2][8][4];
#pragma unroll
    for (int mf = 0; mf < 2; mf++)
#pragma unroll
        for (int nf = 0; nf < 8; nf++)
#pragma unroll
            for (int q = 0; q < 4; q++) acc[mf][nf][q] = 0.0f;

    auto prefetch_half = [&](int h, float* buf) {
#pragma unroll
        for (int t = 0; t < 8; t++) {
            int cc = tid + 256 * t;                 // 2048 16B chunks
            int k = cc >> 4, grp = cc & 15;
            uint32_t dst = (uint32_t)__cvta_generic_to_shared(buf + k * BSTR + grp * 4);
            size_t src = (size_t)__cvta_generic_to_global(g_B + (size_t)(h * 128 + k) * 64 + grp * 4);
            asm volatile("cp.async.cg.shared.global [%0], [%1], 16;" :: "r"(dst), "l"(src));
        }
    };
    auto prefetch_pairs = [&](int c, int bi) {
        if (tid < 32) {
            uint32_t dst = (uint32_t)__cvta_generic_to_shared(pbuf + bi * 128 + tid * 4);
            size_t src = (size_t)__cvta_generic_to_global(g_pair + c * 128 + tid * 4);
            asm volatile("cp.async.ca.shared.global [%0], [%1], 16;" :: "r"(dst), "l"(src));
        }
    };

    // Prologue: G0 = {pairs(0), Bh(0)}
    prefetch_pairs(0, 0);
    prefetch_half(0, bh0);
    asm volatile("cp.async.commit_group;" ::: "memory");

    // MMA over one 64-r half from buffer `cur`, chunk-local k-step base ksb (0 or 8)
    auto mma_half = [&](const float* cur) {
#pragma unroll
        for (int klp = 0; klp < 4; klp++) {
            uint32_t bq[8][4];
#pragma unroll
            for (int nf = 0; nf < 8; nf++) {
                int n0 = wn * 64 + nf * 8 + gid;
                float4 v = *(const float4*)(cur + n0 * BSTR + klp * 16 + tig * 4);
                bq[nf][0] = __float_as_uint(v.x);
                bq[nf][1] = __float_as_uint(v.y);
                bq[nf][2] = __float_as_uint(v.z);
                bq[nf][3] = __float_as_uint(v.w);
            }
            return_point:;
#pragma unroll
            for (int s = 0; s < 2; s++) {
                // chunk-level k-step:
                // handled by caller passing A group base; here we reconstruct:
                // (set below via captured variable)
                ;
            }
            (void)bq; // placeholder (real loop emitted below)
        }
    };
    (void)mma_half; // not used; real code inline below for clarity

    for (int c = 0; c < NCHUNK; ++c) {
        const uint32_t* pcur = pbuf + (c & 1) * 128;

        __syncthreads();                                    // prior MMA done (bh1, A free)
        // G(2c+1): Bh(2c+1) (+ pairs(c+1))
        prefetch_half(2 * c + 1, bh1);
        if (c + 1 < NCHUNK) prefetch_pairs(c + 1, (c + 1) & 1);
        asm volatile("cp.async.commit_group;" ::: "memory");
        asm volatile("cp.async.wait_group 1;" ::: "memory");  // Bh(2c), pairs(c) done
        __syncthreads();                                      // visibility

        // ---- cooperative A build: A[z,r]=tf32(f_i*f_j) in fragment order ----
#pragma unroll
        for (int step = 0; step < 16; step++) {
            int g = step * 8 + warp;               // 0..127: g = wmq*32 + ksq*2 + mfq
            int mfq = g & 1;
            int ksq = (g >> 1) & 15;
            int wmq = g >> 5;
            uint32_t p0 = pcur[ksq * 8 + tig];
            uint32_t p1 = pcur[ksq * 8 + tig + 4];
            int i0 = p0 & 0xFFFF, j0 = p0 >> 16;
            int i1 = p1 & 0xFFFF, j1 = p1 >> 16;
            const float* fz0 = fsm + (wmq * 32 + mfq * 16 + gid) * FSTRF;
            const float* fz8 = fz0 + 8 * FSTRF;
            float4 v;
            v.x = __uint_as_float(f2tf32(fz0[i0] * fz0[j0]));
            v.y = __uint_as_float(f2tf32(fz8[i0] * fz8[j0]));
            v.z = __uint_as_float(f2tf32(fz0[i1] * fz0[j1]));
            v.w = __uint_as_float(f2tf32(fz8[i1] * fz8[j1]));
            *(float4*)(A_sm + (size_t)(step * 256 + tid) * 4) = v;
        }
        __syncthreads();                                      // A ready

        // ---- MMA half 0 (chunk k-steps 0..7, buffer bh0) ----
#pragma unroll
        for (int klp = 0; klp < 4; klp++) {
            uint32_t bq[8][4];
#pragma unroll
            for (int nf = 0; nf < 8; nf++) {
                int n0 = wn * 64 + nf * 8 + gid;
                float4 v = *(const float4*)(bh0 + n0 * BSTR + klp * 16 + tig * 4);
                bq[nf][0] = __float_as_uint(v.x);
                bq[nf][1] = __float_as_uint(v.y);
                bq[nf][2] = __float_as_uint(v.z);
                bq[nf][3] = __float_as_uint(v.w);
            }
#pragma unroll
            for (int s = 0; s < 2; s++) {
                int ks = klp * 2 + s;                         // chunk-level 0..7
#pragma unroll
                for (int mf = 0; mf < 2; mf++) {
                    int g = wm * 32 + ks * 2 + mf;
                    const float4 av = *(const float4*)(A_sm + (size_t)g * 128 + lane * 4);
                    uint32_t a[4] = { __float_as_uint(av.x), __float_as_uint(av.y),
                                      __float_as_uint(av.z), __float_as_uint(av.w) };
#pragma unroll
                    for (int nf = 0; nf < 8; nf++) {
                        uint32_t bb[2] = { bq[nf][2 * s], bq[nf][2 * s + 1] };
                        mma_tf32(acc[mf][nf], a, bb);
                    }
                }
            }
        }
        __syncthreads();                                      // bh0 free

        // G(2c+2): Bh(2c+2)
        if (2 * c + 2 < NHALF) {
            prefetch_half(2 * c + 2, bh0);
            asm volatile("cp.async.commit_group;" ::: "memory");
            asm volatile("cp.async.wait_group 1;" ::: "memory");  // Bh(2c+1) done
        } else {
            asm volatile("cp.async.wait_group 0;" ::: "memory");
        }
        __syncthreads();                                      // visibility

        // ---- MMA half 1 (chunk k-steps 8..15, buffer bh1) ----
#pragma unroll
        for (int klp = 0; klp < 4; klp++) {
            uint32_t bq[8][4];
#pragma unroll
            for (int nf = 0; nf < 8; nf++) {
                int n0 = wn * 64 + nf * 8 + gid;
                float4 v = *(const float4*)(bh1 + n0 * BSTR + klp * 16 + tig * 4);
                bq[nf][0] = __float_as_uint(v.x);
                bq[nf][1] = __float_as_uint(v.y);
                bq[nf][2] = __float_as_uint(v.z);
                bq[nf][3] = __float_as_uint(v.w);
            }
#pragma unroll
            for (int s = 0; s < 2; s++) {
                int ks = 8 + klp * 2 + s;                     // chunk-level 8..15
#pragma unroll
                for (int mf = 0; mf < 2; mf++) {
                    int g = wm * 32 + ks * 2 + mf;
                    const float4 av = *(const float4*)(A_sm + (size_t)g * 128 + lane * 4);
                    uint32_t a[4] = { __float_as_uint(av.x), __float_as_uint(av.y),
                                      __float_as_uint(av.z), __float_as_uint(av.w) };
#pragma unroll
                    for (int nf = 0; nf < 8; nf++) {
                        uint32_t bb[2] = { bq[nf][2 * s], bq[nf][2 * s + 1] };
                        mma_tf32(acc[mf][nf], a, bb);
                    }
                }
            }
        }
    }

    // Epilogue
#pragma unroll
    for (int mf = 0; mf < 2; mf++) {
        int r0 = wm * 32 + mf * 16 + gid;
#pragma unroll
        for (int nf = 0; nf < 8; nf++) {
            int c0 = wn * 64 + nf * 8 + 2 * tig;
            out[(zbase + r0) * KOUT + c0]         = acc[mf][nf][0];
            out[(zbase + r0) * KOUT + c0 + 1]     = acc[mf][nf][1];
            out[(zbase + r0 + 8) * KOUT + c0]     = acc[mf][nf][2];
            out[(zbase + r0 + 8) * KOUT + c0 + 1] = acc[mf][nf][3];
        }
    }
}

// ---------------------------------------------------------------------------
extern "C" void kernel_launch(void* const* d_in, const int* in_sizes, int n_in,
                              void* d_out, int out_size) {
    const float* feat = nullptr;
    const float* W    = nullptr;
    const float* T    = nullptr;
    for (int i = 0; i < n_in; i++) {
        if      (in_sizes[i] == ZB * NIN)   feat = (const float*)d_in[i];
        else if (in_sizes[i] == KOUT * DTS) W    = (const float*)d_in[i];
        else if (in_sizes[i] == DTS * NNF)  T    = (const float*)d_in[i];
    }
    float* out = (float*)d_out;

    cudaFuncSetAttribute(stage2_kernel,
                         cudaFuncAttributeMaxDynamicSharedMemorySize, S2_SMEM);

    build_pairs_kernel<<<128, 128>>>();
    stage1_kernel<<<128, 256>>>(W, T);
    pack_kernel<<<dim3(NHALF, KOUT), 64>>>();
    stage2_kernel<<<128, 256, S2_SMEM>>>(feat, out);
}